// round 15
// baseline (speedup 1.0000x reference)
#include <cuda_runtime.h>
#include <cuda_fp16.h>
#include <mma.h>
#include <math.h>

using namespace nvcuda;

#define NN 100000
#define NNP 100096           // padded to multiple of 128 for wmma tiles
#define NE 3200000
#define D1 256
#define D2 64
#define NPARTMAX 512

// dynamic smem layout for k_mlp
#define ACT_STRIDE 264
#define ACT_BYTES  (128 * ACT_STRIDE * 2)                 // 67584
#define UNION_BYTES 36864                                  // max(As+Bs, Cs, Bs2+..., Cs2)
#define SMEM_MLP   (ACT_BYTES + UNION_BYTES)              // 104448

// ---------------- static device scratch ----------------
__device__ int    g_cnt[NN];
__device__ int    g_woff[NN];
__device__ int    g_rowptr[NN + 1];
__device__ int    g_part[NPARTMAX];
__device__ int    g_col[NE];
__device__ float  g_dinv1[NN];
__device__ float  g_dinv2[NN];
__device__ __half g_xh[(size_t)NN * D1];     // u0 = dinv1[i] * x[i,:] in half
__device__ __half g_h1[(size_t)NN * D1];     // u1 = dinv1^2 * (A u0)
__device__ __half g_h2[(size_t)NNP * D1];    // coeff * dinv1 * (A u1)  (pad rows stay 0)
__device__ __half g_w1h[D1 * D1];            // W1 half
__device__ __half g_w2h[D1 * D2];            // W2 half
__device__ __half g_gh[(size_t)NNP * D2];    // dinv2[i] * (act@W2)[i,:] in half

// ---------------- helpers ----------------
__device__ __forceinline__ float selu_f(float x) {
    const float sc = 1.0507009873554804934f;
    const float al = 1.6732632423543772848f;
    return x > 0.f ? sc * x : sc * al * expm1f(x);
}

__device__ __forceinline__ void addh8(float2 a[4], float4 v) {
    __half2* hp = (__half2*)&v;
#pragma unroll
    for (int q = 0; q < 4; q++) {
        float2 f = __half22float2(hp[q]);
        a[q].x += f.x;
        a[q].y += f.y;
    }
}

__device__ __forceinline__ uint2 f4_to_h4(float4 v) {
    __half2 h0 = __floats2half2_rn(v.x, v.y);
    __half2 h1 = __floats2half2_rn(v.z, v.w);
    return make_uint2(*(unsigned*)&h0, *(unsigned*)&h1);
}

// ---------------- preprocessing ----------------
__global__ void k_count(const int* __restrict__ dst, const float* __restrict__ W1,
                        const float* __restrict__ W2, int e) {
    int stride = gridDim.x * blockDim.x;
    int gtid = blockIdx.x * blockDim.x + threadIdx.x;
    int e4 = e >> 2;
    const int4* dst4 = (const int4*)dst;
    for (int j = gtid; j < e4; j += stride) {
        int4 d = __ldg(dst4 + j);
        atomicAdd(&g_cnt[d.x], 1);
        atomicAdd(&g_cnt[d.y], 1);
        atomicAdd(&g_cnt[d.z], 1);
        atomicAdd(&g_cnt[d.w], 1);
    }
    for (int j = (e4 << 2) + gtid; j < e; j += stride)
        atomicAdd(&g_cnt[dst[j]], 1);
    if (gtid < (D1 * D1) / 4) ((uint2*)g_w1h)[gtid] = f4_to_h4(__ldg(((const float4*)W1) + gtid));
    if (gtid < (D1 * D2) / 4) ((uint2*)g_w2h)[gtid] = f4_to_h4(__ldg(((const float4*)W2) + gtid));
}

__global__ void k_dinvreduce(int n) {
    __shared__ int s[256];
    int t = threadIdx.x;
    int i = blockIdx.x * 256 + t;
    int d = 0;
    if (i < n) {
        d = g_cnt[i];
        g_dinv1[i] = d > 0 ? rsqrtf((float)d) : 0.f;
        g_dinv2[i] = rsqrtf((float)(d + 1));
    }
    s[t] = d;
    __syncthreads();
    for (int o = 128; o; o >>= 1) { if (t < o) s[t] += s[t + o]; __syncthreads(); }
    if (t == 0) g_part[blockIdx.x] = s[0];
}

__global__ void k_scatter(int nparts, int n) {
    __shared__ int spart[NPARTMAX];
    __shared__ int s[256];
    __shared__ int red[8];
    int t = threadIdx.x;
    int b = blockIdx.x;

    for (int i = t; i < nparts; i += 256) spart[i] = g_part[i];
    __syncthreads();

    int loc = 0;
    for (int i = t; i < b; i += 256) loc += spart[i];
#pragma unroll
    for (int o = 16; o; o >>= 1) loc += __shfl_xor_sync(~0u, loc, o);
    if ((t & 31) == 0) red[t >> 5] = loc;
    __syncthreads();
    int blockpre = red[0] + red[1] + red[2] + red[3] + red[4] + red[5] + red[6] + red[7];

    if (b == 0 && t == 0) {
        int tot = 0;
        for (int i = 0; i < nparts; i++) tot += spart[i];
        g_rowptr[n] = tot;
    }

    int i = b * 256 + t;
    int v = (i < n) ? g_cnt[i] : 0;
    s[t] = v;
    __syncthreads();
    for (int o = 1; o < 256; o <<= 1) {
        int x = (t >= o) ? s[t - o] : 0;
        __syncthreads();
        s[t] += x;
        __syncthreads();
    }
    if (i < n) {
        int rp = blockpre + s[t] - v;
        g_rowptr[i] = rp;
        g_woff[i] = rp;
    }
}

// fused CSR fill (2 edges/thread) + x->half conversion, striped 3:1
__global__ void k_fillconv(const int* __restrict__ src, const int* __restrict__ dst,
                           const float* __restrict__ x, int e, int n, int nGroups) {
    int g    = blockIdx.x >> 2;
    int slot = blockIdx.x & 3;
    if (slot != 3) {
        int pair = (g * 3 + slot) * 256 + threadIdx.x;
        int i0 = pair * 2;
        if (i0 + 1 < e) {
            int2 s2 = __ldg((const int2*)(src) + pair);
            int2 d2 = __ldg((const int2*)(dst) + pair);
            int p0 = atomicAdd(&g_woff[d2.x], 1);
            int p1 = atomicAdd(&g_woff[d2.y], 1);
            g_col[p0] = s2.x;
            g_col[p1] = s2.y;
        } else if (i0 < e) {
            int p = atomicAdd(&g_woff[dst[i0]], 1);
            g_col[p] = src[i0];
        }
    } else {
        int stride = nGroups * 256;
        int total = n * (D1 / 4);
        for (int i = g * 256 + threadIdx.x; i < total; i += stride) {
            int row = i >> 6;
            float s = __ldg(g_dinv1 + row);
            float4 v = __ldg(((const float4*)x) + i);
            v.x *= s; v.y *= s; v.z *= s; v.w *= s;
            ((uint2*)g_xh)[i] = f4_to_h4(v);
            if (i < n) g_cnt[i] = 0;
        }
    }
}

// ---------------- weightless 256-dim propagation hop ----------------
template<bool SQUARED>
__global__ void __launch_bounds__(256) k_hop_h(
    const __half* __restrict__ xin, __half* __restrict__ xout,
    const float* __restrict__ dinv, const int* __restrict__ rowptr,
    const int* __restrict__ colidx, float coeff, int n)
{
    int node = (blockIdx.x * blockDim.x + threadIdx.x) >> 5;
    int lane = threadIdx.x & 31;
    if (node >= n) return;
    int beg = rowptr[node], end = rowptr[node + 1];

    float2 a[4];
#pragma unroll
    for (int q = 0; q < 4; q++) a[q] = make_float2(0.f, 0.f);

    for (int e0 = beg; e0 < end; e0 += 32) {
        int idx = e0 + lane;
        int c = (idx < end) ? colidx[idx] : 0;
        int cnt = min(32, end - e0);
        int j = 0;
        for (; j + 8 <= cnt; j += 8) {
            int cc[8];
#pragma unroll
            for (int q = 0; q < 8; q++) cc[q] = __shfl_sync(~0u, c, j + q);
            float4 v[8];
#pragma unroll
            for (int q = 0; q < 8; q++)
                v[q] = __ldg(((const float4*)(xin + (size_t)cc[q] * D1)) + lane);
#pragma unroll
            for (int q = 0; q < 8; q++) addh8(a, v[q]);
        }
        for (; j < cnt; j++) {
            int cj = __shfl_sync(~0u, c, j);
            addh8(a, __ldg(((const float4*)(xin + (size_t)cj * D1)) + lane));
        }
    }

    float d = __ldg(dinv + node);
    float s = SQUARED ? d * d : coeff * d;
    __half2 o0 = __floats2half2_rn(s * a[0].x, s * a[0].y);
    __half2 o1 = __floats2half2_rn(s * a[1].x, s * a[1].y);
    __half2 o2 = __floats2half2_rn(s * a[2].x, s * a[2].y);
    __half2 o3 = __floats2half2_rn(s * a[3].x, s * a[3].y);
    uint4 u;
    u.x = *(unsigned*)&o0; u.y = *(unsigned*)&o1;
    u.z = *(unsigned*)&o2; u.w = *(unsigned*)&o3;
    ((uint4*)(xout + (size_t)node * D1))[lane] = u;
}

// ---------------- fused MLP: gh = dinv2 * (selu(h2@W1 + b1) @ W2) ----------------
// Per block: 128 rows. Phase 1/2: gemm1 column halves -> act smem (half).
// Phase 3: act(smem) @ W2 -> gh. acth global buffer eliminated.
__global__ void __launch_bounds__(256) k_mlp(
    const __half* __restrict__ A, const __half* __restrict__ B1,
    const float* __restrict__ bias, const __half* __restrict__ B2,
    const float* __restrict__ dinv2, __half* __restrict__ Cg, int n)
{
    const int BM = 128, BK = 32;
    extern __shared__ __align__(16) char smem_dyn[];
    __half (*actS)[ACT_STRIDE] = reinterpret_cast<__half(*)[ACT_STRIDE]>(smem_dyn);
    char* un = smem_dyn + ACT_BYTES;
    __half (*As)[BK + 8]  = reinterpret_cast<__half(*)[BK + 8]>(un);            // 10240 B
    __half (*Bs)[128 + 8] = reinterpret_cast<__half(*)[128 + 8]>(un + 10240);   // 8704 B
    float  (*Cs)[68]      = reinterpret_cast<float(*)[68]>(un);                 // 34816 B
    __half (*Bs2)[D2 + 8] = reinterpret_cast<__half(*)[D2 + 8]>(un);            // 4608 B
    float  (*Cs2)[36]     = reinterpret_cast<float(*)[36]>(un + 4608);          // 36864-4608 fits? 8*32*36*4=36864 > 32256!

    // NOTE: Cs2 must fit: place Cs2 at un (reuse whole union after Bs2 is done per-tile is
    // unsafe; instead stage gemm2 epilogue through Cs layout (68-stride, 128 rows) which fits.
    (void)Cs2;

    int tid  = threadIdx.x;
    int warp = tid >> 5;
    int lane = tid & 31;
    int wm = warp >> 1;
    int wn = warp & 1;
    int bm = blockIdx.x * BM;

    int ra = tid >> 2, ca = (tid & 3) * 8;        // A: rows ra, ra+64
    int rb = tid >> 4, cb = (tid & 15) * 8;       // B1: rows rb, rb+16

    // ---- phases 1 & 2: gemm1 halves ----
    for (int phase = 0; phase < 2; phase++) {
        int bn = phase * 128;

        wmma::fragment<wmma::accumulator, 16, 16, 16, float> acc[2][4];
#pragma unroll
        for (int r = 0; r < 2; r++)
#pragma unroll
            for (int c = 0; c < 4; c++) wmma::fill_fragment(acc[r][c], 0.f);

        uint4 pa0 = *(const uint4*)(A + (size_t)(bm + ra) * D1 + ca);
        uint4 pa1 = *(const uint4*)(A + (size_t)(bm + ra + 64) * D1 + ca);
        uint4 pb0 = *(const uint4*)(B1 + (size_t)rb * D1 + bn + cb);
        uint4 pb1 = *(const uint4*)(B1 + (size_t)(rb + 16) * D1 + bn + cb);

        for (int k0 = 0; k0 < D1; k0 += BK) {
            *(uint4*)&As[ra][ca]      = pa0;
            *(uint4*)&As[ra + 64][ca] = pa1;
            *(uint4*)&Bs[rb][cb]      = pb0;
            *(uint4*)&Bs[rb + 16][cb] = pb1;
            __syncthreads();

            int kn = k0 + BK;
            if (kn < D1) {
                pa0 = *(const uint4*)(A + (size_t)(bm + ra) * D1 + kn + ca);
                pa1 = *(const uint4*)(A + (size_t)(bm + ra + 64) * D1 + kn + ca);
                pb0 = *(const uint4*)(B1 + (size_t)(kn + rb) * D1 + bn + cb);
                pb1 = *(const uint4*)(B1 + (size_t)(kn + rb + 16) * D1 + bn + cb);
            }
#pragma unroll
            for (int kk = 0; kk < BK; kk += 16) {
                wmma::fragment<wmma::matrix_a, 16, 16, 16, __half, wmma::row_major> af[2];
                wmma::fragment<wmma::matrix_b, 16, 16, 16, __half, wmma::row_major> bf[4];
#pragma unroll
                for (int r = 0; r < 2; r++)
                    wmma::load_matrix_sync(af[r], &As[wm * 32 + r * 16][kk], BK + 8);
#pragma unroll
                for (int c = 0; c < 4; c++)
                    wmma::load_matrix_sync(bf[c], &Bs[kk][wn * 64 + c * 16], 128 + 8);
#pragma unroll
                for (int r = 0; r < 2; r++)
#pragma unroll
                    for (int c = 0; c < 4; c++)
                        wmma::mma_sync(acc[r][c], af[r], bf[c], acc[r][c]);
            }
            __syncthreads();
        }

        // epilogue: bias + SELU -> actS (half), via Cs staging (union, As/Bs dead)
        int colbase = wn * 64;     // within the 128-col half
        float bl[32];
        {
            int cb2 = bn + colbase + (lane & 1) * 32;
#pragma unroll
            for (int ch = 0; ch < 8; ch++) {
                float4 b4 = __ldg((const float4*)(bias + cb2 + ch * 4));
                bl[ch * 4 + 0] = b4.x; bl[ch * 4 + 1] = b4.y;
                bl[ch * 4 + 2] = b4.z; bl[ch * 4 + 3] = b4.w;
            }
        }
#pragma unroll
        for (int r = 0; r < 2; r++) {
#pragma unroll
            for (int c = 0; c < 4; c++)
                wmma::store_matrix_sync(&Cs[warp * 16][c * 16], acc[r][c], 68, wmma::mem_row_major);
            __syncwarp();
            int row = lane >> 1;
            int half_sel = (lane & 1) * 32;
            float* rowp = &Cs[warp * 16 + row][half_sel];
            __half* arow = &actS[wm * 32 + r * 16 + row][bn + colbase + half_sel];
#pragma unroll
            for (int ch = 0; ch < 4; ch++) {
                float4 v0 = make_float4(selu_f(rowp[ch * 8 + 0] + bl[ch * 8 + 0]),
                                        selu_f(rowp[ch * 8 + 1] + bl[ch * 8 + 1]),
                                        selu_f(rowp[ch * 8 + 2] + bl[ch * 8 + 2]),
                                        selu_f(rowp[ch * 8 + 3] + bl[ch * 8 + 3]));
                float4 v1 = make_float4(selu_f(rowp[ch * 8 + 4] + bl[ch * 8 + 4]),
                                        selu_f(rowp[ch * 8 + 5] + bl[ch * 8 + 5]),
                                        selu_f(rowp[ch * 8 + 6] + bl[ch * 8 + 6]),
                                        selu_f(rowp[ch * 8 + 7] + bl[ch * 8 + 7]));
                uint2 pa = f4_to_h4(v0);
                uint2 pb = f4_to_h4(v1);
                *(uint4*)(arow + ch * 8) = make_uint4(pa.x, pa.y, pb.x, pb.y);
            }
            __syncwarp();
        }
        __syncthreads();   // Cs (union) free; actS half written
    }

    // ---- phase 3: gemm2 from actS (smem) @ W2 -> gh ----
    {
        wmma::fragment<wmma::accumulator, 16, 16, 16, float> acc[2][2];
#pragma unroll
        for (int r = 0; r < 2; r++)
#pragma unroll
            for (int c = 0; c < 2; c++) wmma::fill_fragment(acc[r][c], 0.f);

        int rb2 = tid >> 3, cb2 = (tid & 7) * 8;   // B2 tile: 32 x 64

        for (int k0 = 0; k0 < D1; k0 += BK) {
            *(uint4*)&Bs2[rb2][cb2] = *(const uint4*)(B2 + (size_t)(k0 + rb2) * D2 + cb2);
            __syncthreads();
#pragma unroll
            for (int kk = 0; kk < BK; kk += 16) {
                wmma::fragment<wmma::matrix_a, 16, 16, 16, __half, wmma::row_major> af[2];
                wmma::fragment<wmma::matrix_b, 16, 16, 16, __half, wmma::row_major> bf[2];
#pragma unroll
                for (int r = 0; r < 2; r++)
                    wmma::load_matrix_sync(af[r], &actS[wm * 32 + r * 16][k0 + kk], ACT_STRIDE);
#pragma unroll
                for (int c = 0; c < 2; c++)
                    wmma::load_matrix_sync(bf[c], &Bs2[kk][wn * 32 + c * 16], D2 + 8);
#pragma unroll
                for (int r = 0; r < 2; r++)
#pragma unroll
                    for (int c = 0; c < 2; c++)
                        wmma::mma_sync(acc[r][c], af[r], bf[c], acc[r][c]);
            }
            __syncthreads();
        }

        // epilogue via Cs (68-stride staging: 64 cols fit)
#pragma unroll
        for (int r = 0; r < 2; r++) {
#pragma unroll
            for (int c = 0; c < 2; c++)
                wmma::store_matrix_sync(&Cs[warp * 16][c * 16], acc[r][c], 68, wmma::mem_row_major);
            __syncwarp();
            int rowl = lane >> 1;                   // 0..15
            int half_sel = (lane & 1) * 32;         // 0 or 32 (of 64 cols)
            int grow_i = bm + wm * 32 + r * 16 + rowl;
            float dv = (grow_i < n) ? __ldg(dinv2 + grow_i) : 0.f;
            float* rowp = &Cs[warp * 16 + rowl][half_sel];
            __half* gout = Cg + (size_t)grow_i * D2 + wn * 32;
            // each lane writes 32 cols? wn splits 64 into two 32-col strips; half_sel
            // splits that strip? No: acc covers cols wn*32..wn*32+31 only (BN=64, 2 frags
            // of 16). Stage layout: Cs cols 0..31 = this warp's 32 cols. half_sel picks 16.
            // Rework: half_sel in {0,32} exceeds 32-col strip; use 16-col split instead.
            (void)half_sel; (void)rowp; (void)gout;
            int hs = (lane & 1) * 16;               // 0 or 16 within 32-col strip
            float* rp = &Cs[warp * 16 + rowl][hs];
            __half* go = Cg + (size_t)grow_i * D2 + wn * 32 + hs;
#pragma unroll
            for (int ch = 0; ch < 2; ch++) {
                float4 v0 = make_float4(dv * rp[ch * 8 + 0], dv * rp[ch * 8 + 1],
                                        dv * rp[ch * 8 + 2], dv * rp[ch * 8 + 3]);
                float4 v1 = make_float4(dv * rp[ch * 8 + 4], dv * rp[ch * 8 + 5],
                                        dv * rp[ch * 8 + 6], dv * rp[ch * 8 + 7]);
                uint2 a2 = f4_to_h4(v0);
                uint2 b2v = f4_to_h4(v1);
                *(uint4*)(go + ch * 8) = make_uint4(a2.x, a2.y, b2v.x, b2v.y);
            }
            __syncwarp();
        }
    }
}

// ---------------- final hop (weightless gather, 16-edge MLP) + bias + log_softmax ----------------
__global__ void __launch_bounds__(256) k_out(
    const float* __restrict__ dinv2,
    const int* __restrict__ rowptr, const int* __restrict__ colidx,
    const float* __restrict__ b2, float* __restrict__ out, int n)
{
    int node = (blockIdx.x * blockDim.x + threadIdx.x) >> 5;
    int lane = threadIdx.x & 31;
    if (node >= n) return;
    int beg = rowptr[node], end = rowptr[node + 1];

    float2 sv = __half22float2(__ldg(((const __half2*)(g_gh + (size_t)node * D2)) + lane));
    float ax = sv.x;
    float ay = sv.y;

    for (int e0 = beg; e0 < end; e0 += 32) {
        int idx = e0 + lane;
        int c = (idx < end) ? colidx[idx] : 0;
        int cnt = min(32, end - e0);
        int j = 0;
        for (; j + 16 <= cnt; j += 16) {
            int cc[16];
#pragma unroll
            for (int q = 0; q < 16; q++) cc[q] = __shfl_sync(~0u, c, j + q);
            float2 v[16];
#pragma unroll
            for (int q = 0; q < 16; q++)
                v[q] = __half22float2(__ldg(((const __half2*)(g_gh + (size_t)cc[q] * D2)) + lane));
#pragma unroll
            for (int q = 0; q < 16; q++) { ax += v[q].x; ay += v[q].y; }
        }
        for (; j < cnt; j++) {
            int cj = __shfl_sync(~0u, c, j);
            float2 v = __half22float2(__ldg(((const __half2*)(g_gh + (size_t)cj * D2)) + lane));
            ax += v.x; ay += v.y;
        }
    }

    float di = __ldg(dinv2 + node);
    float p0 = di * ax + __ldg(b2 + lane * 2);
    float p1 = di * ay + __ldg(b2 + lane * 2 + 1);

    float m = fmaxf(p0, p1);
#pragma unroll
    for (int o = 16; o; o >>= 1) m = fmaxf(m, __shfl_xor_sync(~0u, m, o));
    float esum = expf(p0 - m) + expf(p1 - m);
#pragma unroll
    for (int o = 16; o; o >>= 1) esum += __shfl_xor_sync(~0u, esum, o);
    float lse = m + logf(esum);

    float2 res = make_float2(p0 - lse, p1 - lse);
    ((float2*)(out + (size_t)node * D2))[lane] = res;
}

// ---------------- launch ----------------
extern "C" void kernel_launch(void* const* d_in, const int* in_sizes, int n_in,
                              void* d_out, int out_size) {
    const float* x    = (const float*)d_in[0];
    const int*   esrc = (const int*)d_in[1];
    const int*   edst = (const int*)d_in[2];
    const float* W1   = (const float*)d_in[3];
    const float* b1   = (const float*)d_in[4];
    const float* W2   = (const float*)d_in[5];
    const float* b2   = (const float*)d_in[6];
    float* out = (float*)d_out;

    int n = in_sizes[0] / D1;   // 100000
    int e = in_sizes[1];        // 3200000

    __half *xh, *h1, *h2, *w1h, *w2h, *gh;
    float *dinv1, *dinv2;
    int *rowptr, *colidx;
    cudaGetSymbolAddress((void**)&xh, g_xh);
    cudaGetSymbolAddress((void**)&h1, g_h1);
    cudaGetSymbolAddress((void**)&h2, g_h2);
    cudaGetSymbolAddress((void**)&w1h, g_w1h);
    cudaGetSymbolAddress((void**)&w2h, g_w2h);
    cudaGetSymbolAddress((void**)&gh, g_gh);
    cudaGetSymbolAddress((void**)&dinv1, g_dinv1);
    cudaGetSymbolAddress((void**)&dinv2, g_dinv2);
    cudaGetSymbolAddress((void**)&rowptr, g_rowptr);
    cudaGetSymbolAddress((void**)&colidx, g_col);

    cudaFuncSetAttribute(k_mlp, cudaFuncAttributeMaxDynamicSharedMemorySize, SMEM_MLP);

    int nb = (n + 255) / 256;          // 391
    int hopBlocks = (n * 32 + 255) / 256;

    int fillBlocks = (e + 511) / 512;              // 6250
    int nGroups = (fillBlocks + 2) / 3;            // 2084
    k_count<<<1024, 256>>>(edst, W1, W2, e);
    k_dinvreduce<<<nb, 256>>>(n);
    k_scatter<<<nb, 256>>>(nb, n);
    k_fillconv<<<nGroups * 4, 256>>>(esrc, edst, x, e, n, nGroups);

    // conv1: two weightless hops
    k_hop_h<true ><<<hopBlocks, 256>>>(xh, h1, dinv1, rowptr, colidx, 1.0f, n);
    k_hop_h<false><<<hopBlocks, 256>>>(h1, h2, dinv1, rowptr, colidx, 0.36787944117144233f, n);

    // fused MLP (gemm1 + SELU + gemm2 + dinv2 scale), acth round-trip eliminated
    k_mlp<<<NNP / 128, 256, SMEM_MLP>>>(h2, w1h, b1, w2h, dinv2, gh, n);

    k_out<<<hopBlocks, 256>>>(dinv2, rowptr, colidx, b2, out, n);
}

// round 16
// speedup vs baseline: 1.0021x; 1.0021x over previous
#include <cuda_runtime.h>
#include <cuda_fp16.h>
#include <mma.h>
#include <math.h>

using namespace nvcuda;

#define NN 100000
#define NNP 100096           // padded to multiple of 128 for wmma tiles
#define NE 3200000
#define D1 256
#define D2 64
#define NPARTMAX 512

// ---------------- static device scratch ----------------
// g_cnt is zero on first call and re-zeroed by the convx blocks of k_fillconv.
// g_woff is (re)initialized by k_scatter every call.
__device__ int    g_cnt[NN];
__device__ int    g_woff[NN];
__device__ int    g_rowptr[NN + 1];
__device__ int    g_part[NPARTMAX];
__device__ int    g_col[NE];
__device__ float  g_dinv1[NN];
__device__ float  g_dinv2[NN];
__device__ __half g_xh[(size_t)NN * D1];     // u0 = dinv1[i] * x[i,:] in half
__device__ __half g_h1[(size_t)NN * D1];     // u1 = dinv1^2 * (A u0)
__device__ __half g_h2[(size_t)NNP * D1];    // coeff * dinv1 * (A u1)  (pad rows stay 0)
__device__ __half g_w1h[D1 * D1];            // W1 half
__device__ __half g_w2h[D1 * D2];            // W2 half
__device__ __half g_acth[(size_t)NNP * D1];  // selu(h2@W1+b1) in half
__device__ __half g_gh[(size_t)NNP * D2];    // dinv2[i] * (acth@W2)[i,:] in half

// ---------------- helpers ----------------
__device__ __forceinline__ float selu_f(float x) {
    const float sc = 1.0507009873554804934f;
    const float al = 1.6732632423543772848f;
    return x > 0.f ? sc * x : sc * al * expm1f(x);
}

__device__ __forceinline__ void addh8(float2 a[4], float4 v) {
    __half2* hp = (__half2*)&v;
#pragma unroll
    for (int q = 0; q < 4; q++) {
        float2 f = __half22float2(hp[q]);
        a[q].x += f.x;
        a[q].y += f.y;
    }
}

__device__ __forceinline__ uint2 f4_to_h4(float4 v) {
    __half2 h0 = __floats2half2_rn(v.x, v.y);
    __half2 h1 = __floats2half2_rn(v.z, v.w);
    return make_uint2(*(unsigned*)&h0, *(unsigned*)&h1);
}

// ---------------- preprocessing ----------------
// count in-degrees, 4 edges/thread via int4 (g_cnt pre-zeroed) + convert W1/W2
__global__ void k_count(const int* __restrict__ dst, const float* __restrict__ W1,
                        const float* __restrict__ W2, int e) {
    int stride = gridDim.x * blockDim.x;
    int gtid = blockIdx.x * blockDim.x + threadIdx.x;
    int e4 = e >> 2;
    const int4* dst4 = (const int4*)dst;
    for (int j = gtid; j < e4; j += stride) {
        int4 d = __ldg(dst4 + j);
        atomicAdd(&g_cnt[d.x], 1);
        atomicAdd(&g_cnt[d.y], 1);
        atomicAdd(&g_cnt[d.z], 1);
        atomicAdd(&g_cnt[d.w], 1);
    }
    for (int j = (e4 << 2) + gtid; j < e; j += stride)
        atomicAdd(&g_cnt[dst[j]], 1);
    if (gtid < (D1 * D1) / 4) ((uint2*)g_w1h)[gtid] = f4_to_h4(__ldg(((const float4*)W1) + gtid));
    if (gtid < (D1 * D2) / 4) ((uint2*)g_w2h)[gtid] = f4_to_h4(__ldg(((const float4*)W2) + gtid));
}

__global__ void k_dinvreduce(int n) {
    __shared__ int s[256];
    int t = threadIdx.x;
    int i = blockIdx.x * 256 + t;
    int d = 0;
    if (i < n) {
        d = g_cnt[i];
        g_dinv1[i] = d > 0 ? rsqrtf((float)d) : 0.f;
        g_dinv2[i] = rsqrtf((float)(d + 1));
    }
    s[t] = d;
    __syncthreads();
    for (int o = 128; o; o >>= 1) { if (t < o) s[t] += s[t + o]; __syncthreads(); }
    if (t == 0) g_part[blockIdx.x] = s[0];
}

// writes rowptr AND initializes g_woff = rowptr (fill uses woff directly)
__global__ void k_scatter(int nparts, int n) {
    __shared__ int spart[NPARTMAX];
    __shared__ int s[256];
    __shared__ int red[8];
    int t = threadIdx.x;
    int b = blockIdx.x;

    for (int i = t; i < nparts; i += 256) spart[i] = g_part[i];
    __syncthreads();

    int loc = 0;
    for (int i = t; i < b; i += 256) loc += spart[i];
#pragma unroll
    for (int o = 16; o; o >>= 1) loc += __shfl_xor_sync(~0u, loc, o);
    if ((t & 31) == 0) red[t >> 5] = loc;
    __syncthreads();
    int blockpre = red[0] + red[1] + red[2] + red[3] + red[4] + red[5] + red[6] + red[7];

    if (b == 0 && t == 0) {
        int tot = 0;
        for (int i = 0; i < nparts; i++) tot += spart[i];
        g_rowptr[n] = tot;
    }

    int i = b * 256 + t;
    int v = (i < n) ? g_cnt[i] : 0;
    s[t] = v;
    __syncthreads();
    for (int o = 1; o < 256; o <<= 1) {
        int x = (t >= o) ? s[t - o] : 0;
        __syncthreads();
        s[t] += x;
        __syncthreads();
    }
    if (i < n) {
        int rp = blockpre + s[t] - v;
        g_rowptr[i] = rp;
        g_woff[i] = rp;
    }
}

// fused CSR fill (2 edges/thread via int2) + x->half conversion, striped 3:1.
__global__ void k_fillconv(const int* __restrict__ src, const int* __restrict__ dst,
                           const float* __restrict__ x, int e, int n, int nGroups) {
    int g    = blockIdx.x >> 2;
    int slot = blockIdx.x & 3;
    if (slot != 3) {
        int pair = (g * 3 + slot) * 256 + threadIdx.x;   // pair index (2 edges)
        int i0 = pair * 2;
        if (i0 + 1 < e) {
            int2 s2 = __ldg((const int2*)(src) + pair);
            int2 d2 = __ldg((const int2*)(dst) + pair);
            int p0 = atomicAdd(&g_woff[d2.x], 1);
            int p1 = atomicAdd(&g_woff[d2.y], 1);
            g_col[p0] = s2.x;
            g_col[p1] = s2.y;
        } else if (i0 < e) {
            int p = atomicAdd(&g_woff[dst[i0]], 1);
            g_col[p] = src[i0];
        }
    } else {
        int stride = nGroups * 256;
        int total = n * (D1 / 4);
        for (int i = g * 256 + threadIdx.x; i < total; i += stride) {
            int row = i >> 6;               // 64 float4 groups per row
            float s = __ldg(g_dinv1 + row);
            float4 v = __ldg(((const float4*)x) + i);
            v.x *= s; v.y *= s; v.z *= s; v.w *= s;
            ((uint2*)g_xh)[i] = f4_to_h4(v);
            if (i < n) g_cnt[i] = 0;        // restore for next call
        }
    }
}

// ---------------- weightless 256-dim propagation hop ----------------
template<bool SQUARED>
__global__ void __launch_bounds__(256) k_hop_h(
    const __half* __restrict__ xin, __half* __restrict__ xout,
    const float* __restrict__ dinv, const int* __restrict__ rowptr,
    const int* __restrict__ colidx, float coeff, int n)
{
    int node = (blockIdx.x * blockDim.x + threadIdx.x) >> 5;
    int lane = threadIdx.x & 31;
    if (node >= n) return;
    int beg = rowptr[node], end = rowptr[node + 1];

    float2 a[4];
#pragma unroll
    for (int q = 0; q < 4; q++) a[q] = make_float2(0.f, 0.f);

    for (int e0 = beg; e0 < end; e0 += 32) {
        int idx = e0 + lane;
        int c = (idx < end) ? colidx[idx] : 0;
        int cnt = min(32, end - e0);
        int j = 0;
        for (; j + 8 <= cnt; j += 8) {
            int cc[8];
#pragma unroll
            for (int q = 0; q < 8; q++) cc[q] = __shfl_sync(~0u, c, j + q);
            float4 v[8];
#pragma unroll
            for (int q = 0; q < 8; q++)
                v[q] = __ldg(((const float4*)(xin + (size_t)cc[q] * D1)) + lane);
#pragma unroll
            for (int q = 0; q < 8; q++) addh8(a, v[q]);
        }
        for (; j < cnt; j++) {
            int cj = __shfl_sync(~0u, c, j);
            addh8(a, __ldg(((const float4*)(xin + (size_t)cj * D1)) + lane));
        }
    }

    float d = __ldg(dinv + node);
    float s = SQUARED ? d * d : coeff * d;
    __half2 o0 = __floats2half2_rn(s * a[0].x, s * a[0].y);
    __half2 o1 = __floats2half2_rn(s * a[1].x, s * a[1].y);
    __half2 o2 = __floats2half2_rn(s * a[2].x, s * a[2].y);
    __half2 o3 = __floats2half2_rn(s * a[3].x, s * a[3].y);
    uint4 u;
    u.x = *(unsigned*)&o0; u.y = *(unsigned*)&o1;
    u.z = *(unsigned*)&o2; u.w = *(unsigned*)&o3;
    ((uint4*)(xout + (size_t)node * D1))[lane] = u;
}

// ---------------- GEMM1 (reg-prefetch pipelined) + fused bias/SELU -> half ----------------
__global__ void __launch_bounds__(256) k_gemm1(
    const __half* __restrict__ A, const __half* __restrict__ B,
    const float* __restrict__ bias, __half* __restrict__ Cg)
{
    const int BM = 128, BN = 128, BK = 32;
    const int AS_BYTES = BM * (BK + 8) * 2;
    const int BS_BYTES = BK * (BN + 8) * 2;
    const int CS_BYTES = 8 * 16 * 68 * 4;
    __shared__ __align__(16) char smem_buf[CS_BYTES > AS_BYTES + BS_BYTES ? CS_BYTES : AS_BYTES + BS_BYTES];

    __half (*As)[BK + 8] = reinterpret_cast<__half(*)[BK + 8]>(smem_buf);
    __half (*Bs)[BN + 8] = reinterpret_cast<__half(*)[BN + 8]>(smem_buf + AS_BYTES);
    float  (*Cs)[68]     = reinterpret_cast<float(*)[68]>(smem_buf);

    int tid  = threadIdx.x;
    int warp = tid >> 5;
    int lane = tid & 31;
    int wm = warp >> 1;
    int wn = warp & 1;
    int bm = blockIdx.x * BM;
    int bn = blockIdx.y * BN;

    int ra = tid >> 2, ca = (tid & 3) * 8;        // A: rows ra, ra+64
    int rb = tid >> 4, cb = (tid & 15) * 8;       // B: rows rb, rb+16

    wmma::fragment<wmma::accumulator, 16, 16, 16, float> acc[2][4];
#pragma unroll
    for (int r = 0; r < 2; r++)
#pragma unroll
        for (int c = 0; c < 4; c++) wmma::fill_fragment(acc[r][c], 0.f);

    uint4 pa0 = *(const uint4*)(A + (size_t)(bm + ra) * D1 + ca);
    uint4 pa1 = *(const uint4*)(A + (size_t)(bm + ra + 64) * D1 + ca);
    uint4 pb0 = *(const uint4*)(B + (size_t)rb * D1 + bn + cb);
    uint4 pb1 = *(const uint4*)(B + (size_t)(rb + 16) * D1 + bn + cb);

    for (int k0 = 0; k0 < D1; k0 += BK) {
        *(uint4*)&As[ra][ca]      = pa0;
        *(uint4*)&As[ra + 64][ca] = pa1;
        *(uint4*)&Bs[rb][cb]      = pb0;
        *(uint4*)&Bs[rb + 16][cb] = pb1;
        __syncthreads();

        int kn = k0 + BK;
        if (kn < D1) {   // prefetch next tile while mma runs
            pa0 = *(const uint4*)(A + (size_t)(bm + ra) * D1 + kn + ca);
            pa1 = *(const uint4*)(A + (size_t)(bm + ra + 64) * D1 + kn + ca);
            pb0 = *(const uint4*)(B + (size_t)(kn + rb) * D1 + bn + cb);
            pb1 = *(const uint4*)(B + (size_t)(kn + rb + 16) * D1 + bn + cb);
        }
#pragma unroll
        for (int kk = 0; kk < BK; kk += 16) {
            wmma::fragment<wmma::matrix_a, 16, 16, 16, __half, wmma::row_major> af[2];
            wmma::fragment<wmma::matrix_b, 16, 16, 16, __half, wmma::row_major> bf[4];
#pragma unroll
            for (int r = 0; r < 2; r++)
                wmma::load_matrix_sync(af[r], &As[wm * 32 + r * 16][kk], BK + 8);
#pragma unroll
            for (int c = 0; c < 4; c++)
                wmma::load_matrix_sync(bf[c], &Bs[kk][wn * 64 + c * 16], BN + 8);
#pragma unroll
            for (int r = 0; r < 2; r++)
#pragma unroll
                for (int c = 0; c < 4; c++)
                    wmma::mma_sync(acc[r][c], af[r], bf[c], acc[r][c]);
        }
        __syncthreads();
    }

    int colbase = bn + wn * 64;
    float bl[32];
    {
        int cb2 = colbase + (lane & 1) * 32;
#pragma unroll
        for (int ch = 0; ch < 8; ch++) {
            float4 b4 = __ldg((const float4*)(bias + cb2 + ch * 4));
            bl[ch * 4 + 0] = b4.x; bl[ch * 4 + 1] = b4.y;
            bl[ch * 4 + 2] = b4.z; bl[ch * 4 + 3] = b4.w;
        }
    }
#pragma unroll
    for (int r = 0; r < 2; r++) {
#pragma unroll
        for (int c = 0; c < 4; c++)
            wmma::store_matrix_sync(&Cs[warp * 16][c * 16], acc[r][c], 68, wmma::mem_row_major);
        __syncwarp();
        int row = lane >> 1;
        int half_sel = (lane & 1) * 32;
        float* rowp = &Cs[warp * 16 + row][half_sel];
        size_t grow = (size_t)(bm + wm * 32 + r * 16 + row) * D1 + colbase + half_sel;
#pragma unroll
        for (int ch = 0; ch < 4; ch++) {
            float4 v0 = make_float4(selu_f(rowp[ch * 8 + 0] + bl[ch * 8 + 0]),
                                    selu_f(rowp[ch * 8 + 1] + bl[ch * 8 + 1]),
                                    selu_f(rowp[ch * 8 + 2] + bl[ch * 8 + 2]),
                                    selu_f(rowp[ch * 8 + 3] + bl[ch * 8 + 3]));
            float4 v1 = make_float4(selu_f(rowp[ch * 8 + 4] + bl[ch * 8 + 4]),
                                    selu_f(rowp[ch * 8 + 5] + bl[ch * 8 + 5]),
                                    selu_f(rowp[ch * 8 + 6] + bl[ch * 8 + 6]),
                                    selu_f(rowp[ch * 8 + 7] + bl[ch * 8 + 7]));
            uint2 pa = f4_to_h4(v0);
            uint2 pb = f4_to_h4(v1);
            *(uint4*)(Cg + grow + ch * 8) = make_uint4(pa.x, pa.y, pb.x, pb.y);
        }
        __syncwarp();
    }
}

// ---------------- GEMM2 (reg-prefetch pipelined, half out, dinv2-scaled) ----------------
__global__ void __launch_bounds__(256) k_gemm2(
    const __half* __restrict__ A, const __half* __restrict__ B,
    const float* __restrict__ dinv2, __half* __restrict__ Cg, int n)
{
    const int BM = 128, BN = 64, BK = 32;
    __shared__ __half As[BM][BK + 8];
    __shared__ __half Bs[BK][BN + 8];
    __shared__ float  Cs[8][32][36];

    int tid  = threadIdx.x;
    int warp = tid >> 5;
    int lane = tid & 31;
    int wm = warp >> 1;
    int wn = warp & 1;
    int bm = blockIdx.x * BM;

    int ra = tid >> 2, ca = (tid & 3) * 8;    // A: rows ra, ra+64
    int rb = tid >> 3, cb = (tid & 7) * 8;    // B: row rb

    wmma::fragment<wmma::accumulator, 16, 16, 16, float> acc[2][2];
#pragma unroll
    for (int r = 0; r < 2; r++)
#pragma unroll
        for (int c = 0; c < 2; c++) wmma::fill_fragment(acc[r][c], 0.f);

    uint4 pa0 = *(const uint4*)(A + (size_t)(bm + ra) * D1 + ca);
    uint4 pa1 = *(const uint4*)(A + (size_t)(bm + ra + 64) * D1 + ca);
    uint4 pb0 = *(const uint4*)(B + (size_t)rb * D2 + cb);

    for (int k0 = 0; k0 < D1; k0 += BK) {
        *(uint4*)&As[ra][ca]      = pa0;
        *(uint4*)&As[ra + 64][ca] = pa1;
        *(uint4*)&Bs[rb][cb]      = pb0;
        __syncthreads();

        int kn = k0 + BK;
        if (kn < D1) {
            pa0 = *(const uint4*)(A + (size_t)(bm + ra) * D1 + kn + ca);
            pa1 = *(const uint4*)(A + (size_t)(bm + ra + 64) * D1 + kn + ca);
            pb0 = *(const uint4*)(B + (size_t)(kn + rb) * D2 + cb);
        }
#pragma unroll
        for (int kk = 0; kk < BK; kk += 16) {
            wmma::fragment<wmma::matrix_a, 16, 16, 16, __half, wmma::row_major> af[2];
            wmma::fragment<wmma::matrix_b, 16, 16, 16, __half, wmma::row_major> bf[2];
#pragma unroll
            for (int r = 0; r < 2; r++)
                wmma::load_matrix_sync(af[r], &As[wm * 32 + r * 16][kk], BK + 8);
#pragma unroll
            for (int c = 0; c < 2; c++)
                wmma::load_matrix_sync(bf[c], &Bs[kk][wn * 32 + c * 16], BN + 8);
#pragma unroll
            for (int r = 0; r < 2; r++)
#pragma unroll
                for (int c = 0; c < 2; c++)
                    wmma::mma_sync(acc[r][c], af[r], bf[c], acc[r][c]);
        }
        __syncthreads();
    }

#pragma unroll
    for (int r = 0; r < 2; r++)
#pragma unroll
        for (int c = 0; c < 2; c++)
            wmma::store_matrix_sync(&Cs[warp][r * 16][c * 16], acc[r][c], 36, wmma::mem_row_major);
    __syncwarp();

    int row = bm + wm * 32 + lane;
    float dv = (row < n) ? __ldg(dinv2 + row) : 0.f;
    float* rowp = &Cs[warp][lane][0];
    size_t grow = (size_t)row * D2 + wn * 32;
#pragma unroll
    for (int ch = 0; ch < 4; ch++) {
        float4 v0 = make_float4(dv * rowp[ch * 8 + 0], dv * rowp[ch * 8 + 1],
                                dv * rowp[ch * 8 + 2], dv * rowp[ch * 8 + 3]);
        float4 v1 = make_float4(dv * rowp[ch * 8 + 4], dv * rowp[ch * 8 + 5],
                                dv * rowp[ch * 8 + 6], dv * rowp[ch * 8 + 7]);
        uint2 a = f4_to_h4(v0);
        uint2 b = f4_to_h4(v1);
        *(uint4*)(Cg + grow + ch * 8) = make_uint4(a.x, a.y, b.x, b.y);
    }
}

// ---------------- final hop (weightless gather, 16-edge MLP) + bias + log_softmax ----------------
__global__ void __launch_bounds__(256) k_out(
    const float* __restrict__ dinv2,
    const int* __restrict__ rowptr, const int* __restrict__ colidx,
    const float* __restrict__ b2, float* __restrict__ out, int n)
{
    int node = (blockIdx.x * blockDim.x + threadIdx.x) >> 5;
    int lane = threadIdx.x & 31;
    if (node >= n) return;
    int beg = rowptr[node], end = rowptr[node + 1];

    float2 sv = __half22float2(__ldg(((const __half2*)(g_gh + (size_t)node * D2)) + lane));
    float ax = sv.x;
    float ay = sv.y;

    for (int e0 = beg; e0 < end; e0 += 32) {
        int idx = e0 + lane;
        int c = (idx < end) ? colidx[idx] : 0;
        int cnt = min(32, end - e0);
        int j = 0;
        for (; j + 16 <= cnt; j += 16) {
            int cc[16];
#pragma unroll
            for (int q = 0; q < 16; q++) cc[q] = __shfl_sync(~0u, c, j + q);
            float2 v[16];
#pragma unroll
            for (int q = 0; q < 16; q++)
                v[q] = __half22float2(__ldg(((const __half2*)(g_gh + (size_t)cc[q] * D2)) + lane));
#pragma unroll
            for (int q = 0; q < 16; q++) { ax += v[q].x; ay += v[q].y; }
        }
        for (; j < cnt; j++) {
            int cj = __shfl_sync(~0u, c, j);
            float2 v = __half22float2(__ldg(((const __half2*)(g_gh + (size_t)cj * D2)) + lane));
            ax += v.x; ay += v.y;
        }
    }

    float di = __ldg(dinv2 + node);
    float p0 = di * ax + __ldg(b2 + lane * 2);
    float p1 = di * ay + __ldg(b2 + lane * 2 + 1);

    float m = fmaxf(p0, p1);
#pragma unroll
    for (int o = 16; o; o >>= 1) m = fmaxf(m, __shfl_xor_sync(~0u, m, o));
    float esum = expf(p0 - m) + expf(p1 - m);
#pragma unroll
    for (int o = 16; o; o >>= 1) esum += __shfl_xor_sync(~0u, esum, o);
    float lse = m + logf(esum);

    float2 res = make_float2(p0 - lse, p1 - lse);
    ((float2*)(out + (size_t)node * D2))[lane] = res;
}

// ---------------- launch ----------------
extern "C" void kernel_launch(void* const* d_in, const int* in_sizes, int n_in,
                              void* d_out, int out_size) {
    const float* x    = (const float*)d_in[0];
    const int*   esrc = (const int*)d_in[1];
    const int*   edst = (const int*)d_in[2];
    const float* W1   = (const float*)d_in[3];
    const float* b1   = (const float*)d_in[4];
    const float* W2   = (const float*)d_in[5];
    const float* b2   = (const float*)d_in[6];
    float* out = (float*)d_out;

    int n = in_sizes[0] / D1;   // 100000
    int e = in_sizes[1];        // 3200000

    __half *xh, *h1, *h2, *w1h, *w2h, *acth, *gh;
    float *dinv1, *dinv2;
    int *rowptr, *colidx;
    cudaGetSymbolAddress((void**)&xh, g_xh);
    cudaGetSymbolAddress((void**)&h1, g_h1);
    cudaGetSymbolAddress((void**)&h2, g_h2);
    cudaGetSymbolAddress((void**)&w1h, g_w1h);
    cudaGetSymbolAddress((void**)&w2h, g_w2h);
    cudaGetSymbolAddress((void**)&acth, g_acth);
    cudaGetSymbolAddress((void**)&gh, g_gh);
    cudaGetSymbolAddress((void**)&dinv1, g_dinv1);
    cudaGetSymbolAddress((void**)&dinv2, g_dinv2);
    cudaGetSymbolAddress((void**)&rowptr, g_rowptr);
    cudaGetSymbolAddress((void**)&colidx, g_col);

    int nb = (n + 255) / 256;          // 391
    int hopBlocks = (n * 32 + 255) / 256;

    // fill processes 512 edges/block (2 per thread); stripe 3 fill : 1 convx
    int fillBlocks = (e + 511) / 512;              // 6250
    int nGroups = (fillBlocks + 2) / 3;            // 2084
    k_count<<<1024, 256>>>(edst, W1, W2, e);
    k_dinvreduce<<<nb, 256>>>(n);
    k_scatter<<<nb, 256>>>(nb, n);
    k_fillconv<<<nGroups * 4, 256>>>(esrc, edst, x, e, n, nGroups);

    // conv1: two weightless hops
    k_hop_h<true ><<<hopBlocks, 256>>>(xh, h1, dinv1, rowptr, colidx, 1.0f, n);
    k_hop_h<false><<<hopBlocks, 256>>>(h1, h2, dinv1, rowptr, colidx, 0.36787944117144233f, n);

    // GEMM1 (fused bias+SELU) and GEMM2 (fused dinv2 scale), both pipelined
    dim3 g1(NNP / 128, 4);
    g1.y = 2;
    k_gemm1<<<g1, 256>>>(h2, w1h, b1, acth);
    k_gemm2<<<NNP / 128, 256>>>(acth, w2h, dinv2, gh, n);

    k_out<<<hopBlocks, 256>>>(dinv2, rowptr, colidx, b2, out, n);
}

// round 17
// speedup vs baseline: 1.0160x; 1.0138x over previous
#include <cuda_runtime.h>
#include <cuda_fp16.h>
#include <mma.h>
#include <math.h>

using namespace nvcuda;

#define NN 100000
#define NNP 100096           // padded to multiple of 128 for wmma tiles
#define NE 3200000
#define D1 256
#define D2 64
#define NPARTMAX 512

// ---------------- static device scratch ----------------
// g_cnt is zero on first call and re-zeroed by the convx blocks of k_fillconv.
// g_woff is (re)initialized by k_scatter every call.
__device__ int    g_cnt[NN];
__device__ int    g_woff[NN];
__device__ int    g_rowptr[NN + 1];
__device__ int    g_part[NPARTMAX];
__device__ int    g_col[NE];
__device__ float  g_dinv1[NN];
__device__ float  g_dinv2[NN];
__device__ __half g_xh[(size_t)NN * D1];     // u0 = dinv1[i] * x[i,:] in half
__device__ __half g_h1[(size_t)NN * D1];     // u1 = dinv1^2 * (A u0)
__device__ __half g_h2[(size_t)NNP * D1];    // coeff * dinv1 * (A u1)  (pad rows stay 0)
__device__ __half g_w1h[D1 * D1];            // W1 half
__device__ __half g_w2h[D1 * D2];            // W2 half
__device__ __half g_acth[(size_t)NNP * D1];  // selu(h2@W1+b1) in half
__device__ __half g_gh[(size_t)NNP * D2];    // dinv2[i] * (acth@W2)[i,:] in half

// ---------------- helpers ----------------
__device__ __forceinline__ float selu_f(float x) {
    const float sc = 1.0507009873554804934f;
    const float al = 1.6732632423543772848f;
    return x > 0.f ? sc * x : sc * al * expm1f(x);
}

__device__ __forceinline__ void addh8(float2 a[4], float4 v) {
    __half2* hp = (__half2*)&v;
#pragma unroll
    for (int q = 0; q < 4; q++) {
        float2 f = __half22float2(hp[q]);
        a[q].x += f.x;
        a[q].y += f.y;
    }
}

__device__ __forceinline__ uint2 f4_to_h4(float4 v) {
    __half2 h0 = __floats2half2_rn(v.x, v.y);
    __half2 h1 = __floats2half2_rn(v.z, v.w);
    return make_uint2(*(unsigned*)&h0, *(unsigned*)&h1);
}

// ---------------- preprocessing ----------------
// count in-degrees, 4 edges/thread via int4 (g_cnt pre-zeroed) + convert W1/W2
__global__ void k_count(const int* __restrict__ dst, const float* __restrict__ W1,
                        const float* __restrict__ W2, int e) {
    int stride = gridDim.x * blockDim.x;
    int gtid = blockIdx.x * blockDim.x + threadIdx.x;
    int e4 = e >> 2;
    const int4* dst4 = (const int4*)dst;
    for (int j = gtid; j < e4; j += stride) {
        int4 d = __ldg(dst4 + j);
        atomicAdd(&g_cnt[d.x], 1);
        atomicAdd(&g_cnt[d.y], 1);
        atomicAdd(&g_cnt[d.z], 1);
        atomicAdd(&g_cnt[d.w], 1);
    }
    for (int j = (e4 << 2) + gtid; j < e; j += stride)
        atomicAdd(&g_cnt[dst[j]], 1);
    if (gtid < (D1 * D1) / 4) ((uint2*)g_w1h)[gtid] = f4_to_h4(__ldg(((const float4*)W1) + gtid));
    if (gtid < (D1 * D2) / 4) ((uint2*)g_w2h)[gtid] = f4_to_h4(__ldg(((const float4*)W2) + gtid));
}

__global__ void k_dinvreduce(int n) {
    __shared__ int s[256];
    int t = threadIdx.x;
    int i = blockIdx.x * 256 + t;
    int d = 0;
    if (i < n) {
        d = g_cnt[i];
        g_dinv1[i] = d > 0 ? rsqrtf((float)d) : 0.f;
        g_dinv2[i] = rsqrtf((float)(d + 1));
    }
    s[t] = d;
    __syncthreads();
    for (int o = 128; o; o >>= 1) { if (t < o) s[t] += s[t + o]; __syncthreads(); }
    if (t == 0) g_part[blockIdx.x] = s[0];
}

// writes rowptr AND initializes g_woff = rowptr (fill uses woff directly)
__global__ void k_scatter(int nparts, int n) {
    __shared__ int spart[NPARTMAX];
    __shared__ int s[256];
    __shared__ int red[8];
    int t = threadIdx.x;
    int b = blockIdx.x;

    for (int i = t; i < nparts; i += 256) spart[i] = g_part[i];
    __syncthreads();

    int loc = 0;
    for (int i = t; i < b; i += 256) loc += spart[i];
#pragma unroll
    for (int o = 16; o; o >>= 1) loc += __shfl_xor_sync(~0u, loc, o);
    if ((t & 31) == 0) red[t >> 5] = loc;
    __syncthreads();
    int blockpre = red[0] + red[1] + red[2] + red[3] + red[4] + red[5] + red[6] + red[7];

    if (b == 0 && t == 0) {
        int tot = 0;
        for (int i = 0; i < nparts; i++) tot += spart[i];
        g_rowptr[n] = tot;
    }

    int i = b * 256 + t;
    int v = (i < n) ? g_cnt[i] : 0;
    s[t] = v;
    __syncthreads();
    for (int o = 1; o < 256; o <<= 1) {
        int x = (t >= o) ? s[t - o] : 0;
        __syncthreads();
        s[t] += x;
        __syncthreads();
    }
    if (i < n) {
        int rp = blockpre + s[t] - v;
        g_rowptr[i] = rp;
        g_woff[i] = rp;
    }
}

// fused CSR fill (2 edges/thread via int2) + x->half conversion, striped 3:1.
__global__ void k_fillconv(const int* __restrict__ src, const int* __restrict__ dst,
                           const float* __restrict__ x, int e, int n, int nGroups) {
    int g    = blockIdx.x >> 2;
    int slot = blockIdx.x & 3;
    if (slot != 3) {
        int pair = (g * 3 + slot) * 256 + threadIdx.x;   // pair index (2 edges)
        int i0 = pair * 2;
        if (i0 + 1 < e) {
            int2 s2 = __ldg((const int2*)(src) + pair);
            int2 d2 = __ldg((const int2*)(dst) + pair);
            int p0 = atomicAdd(&g_woff[d2.x], 1);
            int p1 = atomicAdd(&g_woff[d2.y], 1);
            g_col[p0] = s2.x;
            g_col[p1] = s2.y;
        } else if (i0 < e) {
            int p = atomicAdd(&g_woff[dst[i0]], 1);
            g_col[p] = src[i0];
        }
    } else {
        int stride = nGroups * 256;
        int total = n * (D1 / 4);
        for (int i = g * 256 + threadIdx.x; i < total; i += stride) {
            int row = i >> 6;               // 64 float4 groups per row
            float s = __ldg(g_dinv1 + row);
            float4 v = __ldg(((const float4*)x) + i);
            v.x *= s; v.y *= s; v.z *= s; v.w *= s;
            ((uint2*)g_xh)[i] = f4_to_h4(v);
            if (i < n) g_cnt[i] = 0;        // restore for next call
        }
    }
}

// ---------------- weightless 256-dim propagation hop ----------------
template<bool SQUARED>
__global__ void __launch_bounds__(256) k_hop_h(
    const __half* __restrict__ xin, __half* __restrict__ xout,
    const float* __restrict__ dinv, const int* __restrict__ rowptr,
    const int* __restrict__ colidx, float coeff, int n)
{
    int node = (blockIdx.x * blockDim.x + threadIdx.x) >> 5;
    int lane = threadIdx.x & 31;
    if (node >= n) return;
    int beg = rowptr[node], end = rowptr[node + 1];

    float2 a[4];
#pragma unroll
    for (int q = 0; q < 4; q++) a[q] = make_float2(0.f, 0.f);

    for (int e0 = beg; e0 < end; e0 += 32) {
        int idx = e0 + lane;
        int c = (idx < end) ? colidx[idx] : 0;
        int cnt = min(32, end - e0);
        int j = 0;
        for (; j + 8 <= cnt; j += 8) {
            int cc[8];
#pragma unroll
            for (int q = 0; q < 8; q++) cc[q] = __shfl_sync(~0u, c, j + q);
            float4 v[8];
#pragma unroll
            for (int q = 0; q < 8; q++)
                v[q] = __ldg(((const float4*)(xin + (size_t)cc[q] * D1)) + lane);
#pragma unroll
            for (int q = 0; q < 8; q++) addh8(a, v[q]);
        }
        for (; j < cnt; j++) {
            int cj = __shfl_sync(~0u, c, j);
            addh8(a, __ldg(((const float4*)(xin + (size_t)cj * D1)) + lane));
        }
    }

    float d = __ldg(dinv + node);
    float s = SQUARED ? d * d : coeff * d;
    __half2 o0 = __floats2half2_rn(s * a[0].x, s * a[0].y);
    __half2 o1 = __floats2half2_rn(s * a[1].x, s * a[1].y);
    __half2 o2 = __floats2half2_rn(s * a[2].x, s * a[2].y);
    __half2 o3 = __floats2half2_rn(s * a[3].x, s * a[3].y);
    uint4 u;
    u.x = *(unsigned*)&o0; u.y = *(unsigned*)&o1;
    u.z = *(unsigned*)&o2; u.w = *(unsigned*)&o3;
    ((uint4*)(xout + (size_t)node * D1))[lane] = u;
}

// ---------------- GEMM1 (reg-prefetch pipelined) + fused bias/SELU -> half ----------------
__global__ void __launch_bounds__(256) k_gemm1(
    const __half* __restrict__ A, const __half* __restrict__ B,
    const float* __restrict__ bias, __half* __restrict__ Cg)
{
    const int BM = 128, BN = 128, BK = 32;
    const int AS_BYTES = BM * (BK + 8) * 2;
    const int BS_BYTES = BK * (BN + 8) * 2;
    const int CS_BYTES = 8 * 16 * 68 * 4;
    __shared__ __align__(16) char smem_buf[CS_BYTES > AS_BYTES + BS_BYTES ? CS_BYTES : AS_BYTES + BS_BYTES];

    __half (*As)[BK + 8] = reinterpret_cast<__half(*)[BK + 8]>(smem_buf);
    __half (*Bs)[BN + 8] = reinterpret_cast<__half(*)[BN + 8]>(smem_buf + AS_BYTES);
    float  (*Cs)[68]     = reinterpret_cast<float(*)[68]>(smem_buf);

    int tid  = threadIdx.x;
    int warp = tid >> 5;
    int lane = tid & 31;
    int wm = warp >> 1;
    int wn = warp & 1;
    int bm = blockIdx.x * BM;
    int bn = blockIdx.y * BN;

    int ra = tid >> 2, ca = (tid & 3) * 8;        // A: rows ra, ra+64
    int rb = tid >> 4, cb = (tid & 15) * 8;       // B: rows rb, rb+16

    wmma::fragment<wmma::accumulator, 16, 16, 16, float> acc[2][4];
#pragma unroll
    for (int r = 0; r < 2; r++)
#pragma unroll
        for (int c = 0; c < 4; c++) wmma::fill_fragment(acc[r][c], 0.f);

    uint4 pa0 = *(const uint4*)(A + (size_t)(bm + ra) * D1 + ca);
    uint4 pa1 = *(const uint4*)(A + (size_t)(bm + ra + 64) * D1 + ca);
    uint4 pb0 = *(const uint4*)(B + (size_t)rb * D1 + bn + cb);
    uint4 pb1 = *(const uint4*)(B + (size_t)(rb + 16) * D1 + bn + cb);

    for (int k0 = 0; k0 < D1; k0 += BK) {
        *(uint4*)&As[ra][ca]      = pa0;
        *(uint4*)&As[ra + 64][ca] = pa1;
        *(uint4*)&Bs[rb][cb]      = pb0;
        *(uint4*)&Bs[rb + 16][cb] = pb1;
        __syncthreads();

        int kn = k0 + BK;
        if (kn < D1) {   // prefetch next tile while mma runs
            pa0 = *(const uint4*)(A + (size_t)(bm + ra) * D1 + kn + ca);
            pa1 = *(const uint4*)(A + (size_t)(bm + ra + 64) * D1 + kn + ca);
            pb0 = *(const uint4*)(B + (size_t)(kn + rb) * D1 + bn + cb);
            pb1 = *(const uint4*)(B + (size_t)(kn + rb + 16) * D1 + bn + cb);
        }
#pragma unroll
        for (int kk = 0; kk < BK; kk += 16) {
            wmma::fragment<wmma::matrix_a, 16, 16, 16, __half, wmma::row_major> af[2];
            wmma::fragment<wmma::matrix_b, 16, 16, 16, __half, wmma::row_major> bf[4];
#pragma unroll
            for (int r = 0; r < 2; r++)
                wmma::load_matrix_sync(af[r], &As[wm * 32 + r * 16][kk], BK + 8);
#pragma unroll
            for (int c = 0; c < 4; c++)
                wmma::load_matrix_sync(bf[c], &Bs[kk][wn * 64 + c * 16], BN + 8);
#pragma unroll
            for (int r = 0; r < 2; r++)
#pragma unroll
                for (int c = 0; c < 4; c++)
                    wmma::mma_sync(acc[r][c], af[r], bf[c], acc[r][c]);
        }
        __syncthreads();
    }

    int colbase = bn + wn * 64;
    float bl[32];
    {
        int cb2 = colbase + (lane & 1) * 32;
#pragma unroll
        for (int ch = 0; ch < 8; ch++) {
            float4 b4 = __ldg((const float4*)(bias + cb2 + ch * 4));
            bl[ch * 4 + 0] = b4.x; bl[ch * 4 + 1] = b4.y;
            bl[ch * 4 + 2] = b4.z; bl[ch * 4 + 3] = b4.w;
        }
    }
#pragma unroll
    for (int r = 0; r < 2; r++) {
#pragma unroll
        for (int c = 0; c < 4; c++)
            wmma::store_matrix_sync(&Cs[warp * 16][c * 16], acc[r][c], 68, wmma::mem_row_major);
        __syncwarp();
        int row = lane >> 1;
        int half_sel = (lane & 1) * 32;
        float* rowp = &Cs[warp * 16 + row][half_sel];
        size_t grow = (size_t)(bm + wm * 32 + r * 16 + row) * D1 + colbase + half_sel;
#pragma unroll
        for (int ch = 0; ch < 4; ch++) {
            float4 v0 = make_float4(selu_f(rowp[ch * 8 + 0] + bl[ch * 8 + 0]),
                                    selu_f(rowp[ch * 8 + 1] + bl[ch * 8 + 1]),
                                    selu_f(rowp[ch * 8 + 2] + bl[ch * 8 + 2]),
                                    selu_f(rowp[ch * 8 + 3] + bl[ch * 8 + 3]));
            float4 v1 = make_float4(selu_f(rowp[ch * 8 + 4] + bl[ch * 8 + 4]),
                                    selu_f(rowp[ch * 8 + 5] + bl[ch * 8 + 5]),
                                    selu_f(rowp[ch * 8 + 6] + bl[ch * 8 + 6]),
                                    selu_f(rowp[ch * 8 + 7] + bl[ch * 8 + 7]));
            uint2 pa = f4_to_h4(v0);
            uint2 pb = f4_to_h4(v1);
            *(uint4*)(Cg + grow + ch * 8) = make_uint4(pa.x, pa.y, pb.x, pb.y);
        }
        __syncwarp();
    }
}

// ---------------- GEMM2 (reg-prefetch pipelined, half out, dinv2-scaled) ----------------
__global__ void __launch_bounds__(256) k_gemm2(
    const __half* __restrict__ A, const __half* __restrict__ B,
    const float* __restrict__ dinv2, __half* __restrict__ Cg, int n)
{
    const int BM = 128, BN = 64, BK = 32;
    __shared__ __half As[BM][BK + 8];
    __shared__ __half Bs[BK][BN + 8];
    __shared__ float  Cs[8][32][36];

    int tid  = threadIdx.x;
    int warp = tid >> 5;
    int lane = tid & 31;
    int wm = warp >> 1;
    int wn = warp & 1;
    int bm = blockIdx.x * BM;

    int ra = tid >> 2, ca = (tid & 3) * 8;    // A: rows ra, ra+64
    int rb = tid >> 3, cb = (tid & 7) * 8;    // B: row rb

    wmma::fragment<wmma::accumulator, 16, 16, 16, float> acc[2][2];
#pragma unroll
    for (int r = 0; r < 2; r++)
#pragma unroll
        for (int c = 0; c < 2; c++) wmma::fill_fragment(acc[r][c], 0.f);

    uint4 pa0 = *(const uint4*)(A + (size_t)(bm + ra) * D1 + ca);
    uint4 pa1 = *(const uint4*)(A + (size_t)(bm + ra + 64) * D1 + ca);
    uint4 pb0 = *(const uint4*)(B + (size_t)rb * D2 + cb);

    for (int k0 = 0; k0 < D1; k0 += BK) {
        *(uint4*)&As[ra][ca]      = pa0;
        *(uint4*)&As[ra + 64][ca] = pa1;
        *(uint4*)&Bs[rb][cb]      = pb0;
        __syncthreads();

        int kn = k0 + BK;
        if (kn < D1) {
            pa0 = *(const uint4*)(A + (size_t)(bm + ra) * D1 + kn + ca);
            pa1 = *(const uint4*)(A + (size_t)(bm + ra + 64) * D1 + kn + ca);
            pb0 = *(const uint4*)(B + (size_t)(kn + rb) * D2 + cb);
        }
#pragma unroll
        for (int kk = 0; kk < BK; kk += 16) {
            wmma::fragment<wmma::matrix_a, 16, 16, 16, __half, wmma::row_major> af[2];
            wmma::fragment<wmma::matrix_b, 16, 16, 16, __half, wmma::row_major> bf[2];
#pragma unroll
            for (int r = 0; r < 2; r++)
                wmma::load_matrix_sync(af[r], &As[wm * 32 + r * 16][kk], BK + 8);
#pragma unroll
            for (int c = 0; c < 2; c++)
                wmma::load_matrix_sync(bf[c], &Bs[kk][wn * 32 + c * 16], BN + 8);
#pragma unroll
            for (int r = 0; r < 2; r++)
#pragma unroll
                for (int c = 0; c < 2; c++)
                    wmma::mma_sync(acc[r][c], af[r], bf[c], acc[r][c]);
        }
        __syncthreads();
    }

#pragma unroll
    for (int r = 0; r < 2; r++)
#pragma unroll
        for (int c = 0; c < 2; c++)
            wmma::store_matrix_sync(&Cs[warp][r * 16][c * 16], acc[r][c], 36, wmma::mem_row_major);
    __syncwarp();

    int row = bm + wm * 32 + lane;
    float dv = (row < n) ? __ldg(dinv2 + row) : 0.f;
    float* rowp = &Cs[warp][lane][0];
    size_t grow = (size_t)row * D2 + wn * 32;
#pragma unroll
    for (int ch = 0; ch < 4; ch++) {
        float4 v0 = make_float4(dv * rowp[ch * 8 + 0], dv * rowp[ch * 8 + 1],
                                dv * rowp[ch * 8 + 2], dv * rowp[ch * 8 + 3]);
        float4 v1 = make_float4(dv * rowp[ch * 8 + 4], dv * rowp[ch * 8 + 5],
                                dv * rowp[ch * 8 + 6], dv * rowp[ch * 8 + 7]);
        uint2 a = f4_to_h4(v0);
        uint2 b = f4_to_h4(v1);
        *(uint4*)(Cg + grow + ch * 8) = make_uint4(a.x, a.y, b.x, b.y);
    }
}

// ---------------- final hop (weightless gather, 8-edge MLP) + bias + log_softmax ----------------
__global__ void __launch_bounds__(256) k_out(
    const float* __restrict__ dinv2,
    const int* __restrict__ rowptr, const int* __restrict__ colidx,
    const float* __restrict__ b2, float* __restrict__ out, int n)
{
    int node = (blockIdx.x * blockDim.x + threadIdx.x) >> 5;
    int lane = threadIdx.x & 31;
    if (node >= n) return;
    int beg = rowptr[node], end = rowptr[node + 1];

    float2 sv = __half22float2(__ldg(((const __half2*)(g_gh + (size_t)node * D2)) + lane));
    float ax = sv.x;
    float ay = sv.y;

    for (int e0 = beg; e0 < end; e0 += 32) {
        int idx = e0 + lane;
        int c = (idx < end) ? colidx[idx] : 0;
        int cnt = min(32, end - e0);
        int j = 0;
        for (; j + 8 <= cnt; j += 8) {
            int cc[8];
#pragma unroll
            for (int q = 0; q < 8; q++) cc[q] = __shfl_sync(~0u, c, j + q);
            float2 v[8];
#pragma unroll
            for (int q = 0; q < 8; q++)
                v[q] = __half22float2(__ldg(((const __half2*)(g_gh + (size_t)cc[q] * D2)) + lane));
#pragma unroll
            for (int q = 0; q < 8; q++) { ax += v[q].x; ay += v[q].y; }
        }
        for (; j < cnt; j++) {
            int cj = __shfl_sync(~0u, c, j);
            float2 v = __half22float2(__ldg(((const __half2*)(g_gh + (size_t)cj * D2)) + lane));
            ax += v.x; ay += v.y;
        }
    }

    float di = __ldg(dinv2 + node);
    float p0 = di * ax + __ldg(b2 + lane * 2);
    float p1 = di * ay + __ldg(b2 + lane * 2 + 1);

    float m = fmaxf(p0, p1);
#pragma unroll
    for (int o = 16; o; o >>= 1) m = fmaxf(m, __shfl_xor_sync(~0u, m, o));
    float esum = expf(p0 - m) + expf(p1 - m);
#pragma unroll
    for (int o = 16; o; o >>= 1) esum += __shfl_xor_sync(~0u, esum, o);
    float lse = m + logf(esum);

    float2 res = make_float2(p0 - lse, p1 - lse);
    ((float2*)(out + (size_t)node * D2))[lane] = res;
}

// ---------------- launch ----------------
extern "C" void kernel_launch(void* const* d_in, const int* in_sizes, int n_in,
                              void* d_out, int out_size) {
    const float* x    = (const float*)d_in[0];
    const int*   esrc = (const int*)d_in[1];
    const int*   edst = (const int*)d_in[2];
    const float* W1   = (const float*)d_in[3];
    const float* b1   = (const float*)d_in[4];
    const float* W2   = (const float*)d_in[5];
    const float* b2   = (const float*)d_in[6];
    float* out = (float*)d_out;

    int n = in_sizes[0] / D1;   // 100000
    int e = in_sizes[1];        // 3200000

    __half *xh, *h1, *h2, *w1h, *w2h, *acth, *gh;
    float *dinv1, *dinv2;
    int *rowptr, *colidx;
    cudaGetSymbolAddress((void**)&xh, g_xh);
    cudaGetSymbolAddress((void**)&h1, g_h1);
    cudaGetSymbolAddress((void**)&h2, g_h2);
    cudaGetSymbolAddress((void**)&w1h, g_w1h);
    cudaGetSymbolAddress((void**)&w2h, g_w2h);
    cudaGetSymbolAddress((void**)&acth, g_acth);
    cudaGetSymbolAddress((void**)&gh, g_gh);
    cudaGetSymbolAddress((void**)&dinv1, g_dinv1);
    cudaGetSymbolAddress((void**)&dinv2, g_dinv2);
    cudaGetSymbolAddress((void**)&rowptr, g_rowptr);
    cudaGetSymbolAddress((void**)&colidx, g_col);

    int nb = (n + 255) / 256;          // 391
    int hopBlocks = (n * 32 + 255) / 256;

    // fill processes 512 edges/block (2 per thread); stripe 3 fill : 1 convx
    int fillBlocks = (e + 511) / 512;              // 6250
    int nGroups = (fillBlocks + 2) / 3;            // 2084
    k_count<<<1024, 256>>>(edst, W1, W2, e);
    k_dinvreduce<<<nb, 256>>>(n);
    k_scatter<<<nb, 256>>>(nb, n);
    k_fillconv<<<nGroups * 4, 256>>>(esrc, edst, x, e, n, nGroups);

    // conv1: two weightless hops
    k_hop_h<true ><<<hopBlocks, 256>>>(xh, h1, dinv1, rowptr, colidx, 1.0f, n);
    k_hop_h<false><<<hopBlocks, 256>>>(h1, h2, dinv1, rowptr, colidx, 0.36787944117144233f, n);

    // GEMM1 (fused bias+SELU) and GEMM2 (fused dinv2 scale), both pipelined
    dim3 g1(NNP / 128, 2);
    k_gemm1<<<g1, 256>>>(h2, w1h, b1, acth);
    k_gemm2<<<NNP / 128, 256>>>(acth, w2h, dinv2, gh, n);

    k_out<<<hopBlocks, 256>>>(dinv2, rowptr, colidx, b2, out, n);
}